// round 9
// baseline (speedup 1.0000x reference)
#include <cuda_runtime.h>
#include <math.h>
#include <stdint.h>

#define NN   2048
#define KK   16384      // NN * 8
#define TAU  10
#define NB   8

// dense x-vectors for the three matvecs
__device__ __align__(16) float g_x0[KK];
__device__ __align__(16) float g_x1[KK];
__device__ __align__(16) float g_x2[KK];

// ---------------- Threefry-2x32 (JAX-compatible, 20 rounds) ----------------
__host__ __device__ inline uint32_t tf_rotl(uint32_t v, int r) {
    return (v << r) | (v >> (32 - r));
}

__host__ __device__ inline void tf_block(uint32_t k0, uint32_t k1,
                                         uint32_t c0, uint32_t c1,
                                         uint32_t& o0, uint32_t& o1) {
    uint32_t ks2 = k0 ^ k1 ^ 0x1BD11BDAu;
    uint32_t x0 = c0 + k0, x1 = c1 + k1;
#define TF_RND(r) { x0 += x1; x1 = tf_rotl(x1, (r)); x1 ^= x0; }
    TF_RND(13) TF_RND(15) TF_RND(26) TF_RND(6)
    x0 += k1;  x1 += ks2 + 1u;
    TF_RND(17) TF_RND(29) TF_RND(16) TF_RND(24)
    x0 += ks2; x1 += k0 + 2u;
    TF_RND(13) TF_RND(15) TF_RND(26) TF_RND(6)
    x0 += k0;  x1 += k1 + 3u;
    TF_RND(17) TF_RND(29) TF_RND(16) TF_RND(24)
    x0 += k1;  x1 += ks2 + 4u;
    TF_RND(13) TF_RND(15) TF_RND(26) TF_RND(6)
    x0 += ks2; x1 += k0 + 5u;
#undef TF_RND
    o0 = x0; o1 = x1;
}

__device__ inline float tf_uniform(uint32_t k0, uint32_t k1, uint32_t e) {
    uint32_t b1, b2;
    tf_block(k0, k1, 0u, e, b1, b2);
    uint32_t bits = b1 ^ b2;
    return __uint_as_float((bits >> 9) | 0x3f800000u) - 1.0f;
}

// ---------------- Kernel 1: layer-0 input trace ----------------
__global__ void trace_kernel(const float* __restrict__ inp) {
    __shared__ float filt[TAU * NB];
    int tid = threadIdx.x;
    if (tid < TAU * NB) {
        int t = tid / NB, b = tid % NB;
        const float mupi = 1.5707963267948966f;
        const float pif  = 3.14159265358979f;
        float arg = mupi * log1pf((float)t) - mupi * (float)b;
        arg = fminf(fmaxf(arg, -pif), pif);
        filt[tid] = 0.5f * (1.0f + cosf(arg));
    }
    __syncthreads();
    int i = blockIdx.x * blockDim.x + tid;
    if (i < NN) {
        float acc[NB];
#pragma unroll
        for (int b = 0; b < NB; b++) acc[b] = 0.0f;
#pragma unroll
        for (int t = 0; t < TAU; t++) {
            float v = inp[i * TAU + (TAU - 1 - t)];
#pragma unroll
            for (int b = 0; b < NB; b++) acc[b] += v * filt[t * NB + b];
        }
#pragma unroll
        for (int b = 0; b < NB; b++) g_x0[i * NB + b] = acc[b];
    }
}

// ---------------- Kernel 2: unified dense layer ----------------------------
// Exactly the proven layer0 pattern (~83% of HBM spec): plain float4 loads of
// W streaming from DRAM and the L2-resident 64KB x-vector, FMA dot, block
// reduce, thread-0 epilogue (sigmoid + threefry bernoulli + write next dense
// x-vector as [s, 0.5*s, 0,...,0]).
__global__ __launch_bounds__(256) void dense_layer(
    const float* __restrict__ W, const float* __restrict__ bias,
    const float* __restrict__ x_in, float* __restrict__ x_out,
    float* __restrict__ p_out, float* __restrict__ s_out,
    uint32_t key0, uint32_t key1, float f1)
{
    __shared__ float warpsum[8];
    const int row = blockIdx.x;
    const float4* w4 = reinterpret_cast<const float4*>(W + (size_t)row * KK);
    const float4* x4 = reinterpret_cast<const float4*>(x_in);

    float acc = 0.0f;
#pragma unroll
    for (int it = 0; it < 16; it++) {
        int j = it * 256 + threadIdx.x;
        float4 w = w4[j];
        float4 xv = x4[j];
        acc += w.x * xv.x + w.y * xv.y + w.z * xv.z + w.w * xv.w;
    }

#pragma unroll
    for (int off = 16; off > 0; off >>= 1)
        acc += __shfl_down_sync(0xffffffffu, acc, off);
    int lane = threadIdx.x & 31, wid = threadIdx.x >> 5;
    if (lane == 0) warpsum[wid] = acc;
    __syncthreads();

    if (threadIdx.x == 0) {
        float tot = 0.0f;
#pragma unroll
        for (int w = 0; w < 8; w++) tot += warpsum[w];
        float z = tot + bias[row];
        float p = 1.0f / (1.0f + expf(-z));
        float u = tf_uniform(key0, key1, (uint32_t)row);
        float s = (u < p) ? 1.0f : 0.0f;
        p_out[row] = p;
        s_out[row] = s;
        if (x_out) {
            float4* xo = reinterpret_cast<float4*>(x_out + row * NB);
            xo[0] = make_float4(s, s * f1, 0.0f, 0.0f);  // FF_FILT[0,:2]
            xo[1] = make_float4(0.0f, 0.0f, 0.0f, 0.0f); // exact zeros
        }
    }
}

extern "C" void kernel_launch(void* const* d_in, const int* in_sizes, int n_in,
                              void* d_out, int out_size) {
    const float* inp  = (const float*)d_in[0];
    const float* ffw0 = (const float*)d_in[1];
    const float* b0   = (const float*)d_in[3];
    const float* ffw1 = (const float*)d_in[4];
    const float* b1   = (const float*)d_in[6];
    const float* ffw2 = (const float*)d_in[7];
    const float* b2   = (const float*)d_in[9];
    float* out = (float*)d_out;

    // resolve device globals (no allocation; just address lookup is illegal
    // inside capture? cudaGetSymbolAddress is not stream work — it's fine,
    // but do it without sync APIs)
    // We instead pass the globals via device-linked pointers using a small
    // trampoline: device globals are directly addressable from kernels, so
    // pass indices... simplest: use cudaGetSymbolAddress (host-side, not a
    // stream op, graph-capture safe).
    static float *px0 = nullptr, *px1 = nullptr, *px2 = nullptr;
    if (!px0) {
        cudaGetSymbolAddress((void**)&px0, g_x0);
        cudaGetSymbolAddress((void**)&px1, g_x1);
        cudaGetSymbolAddress((void**)&px2, g_x2);
    }

    // root key = (0, 42); partitionable split: key_i = block(root, (0, i))
    uint32_t k0a, k0b, k1a, k1b, k2a, k2b;
    tf_block(0u, 42u, 0u, 0u, k0a, k0b);
    tf_block(0u, 42u, 0u, 1u, k1a, k1b);
    tf_block(0u, 42u, 0u, 2u, k2a, k2b);

    // FF_FILT[0,1]; entries b>=2 are exactly 0 (clip to -pi), b=0 is exactly 1
    const float mupi = 1.5707963267948966f;
    const float pif  = 3.14159265358979f;
    float f1 = 0.5f * (1.0f + cosf(fminf(fmaxf(-mupi, -pif), pif)));  // ~0.5

    // output layout: [p2 | s2 | p0 | p1 | s0 | s1], 6 * 2048 floats
    float* p2 = out;
    float* s2 = out + 2048;
    float* p0 = out + 4096;
    float* p1 = out + 6144;
    float* s0 = out + 8192;
    float* s1 = out + 10240;

    trace_kernel<<<16, 128>>>(inp);
    dense_layer<<<NN, 256>>>(ffw0, b0, px0, px1,    p0, s0, k0a, k0b, f1);
    dense_layer<<<NN, 256>>>(ffw1, b1, px1, px2,    p1, s1, k1a, k1b, f1);
    dense_layer<<<NN, 256>>>(ffw2, b2, px2, nullptr, p2, s2, k2a, k2b, f1);
}